// round 5
// baseline (speedup 1.0000x reference)
#include <cuda_runtime.h>

#define FULL_MASK 0xffffffffu

// Scratch for tree_v, laid out as [B=16][D=256] (head h occupies channels h*32..h*32+31)
__device__ float g_tv[16 * 256];

// ---------------------------------------------------------------------------
// Kernel A: LIF tree. One block per (batch, head): 128 blocks x 256 threads.
// Phase 0: ALL 15 nodes' W (padded stride-33 rows) + b/thr/tau/vres staged
//          into dynamic smem in one batched phase (15 indep LDG.128/thread).
// Phase 1+: warp l owns node l of the current level; all compute from smem.
// ---------------------------------------------------------------------------
__device__ __forceinline__ void node_step_smem(
    float& xk, float& xv, int node, int lane,
    const float* __restrict__ Ws,
    const float* __restrict__ pb, const float* __restrict__ pth,
    const float* __restrict__ pta, const float* __restrict__ pvr)
{
    const float* __restrict__ wrow = Ws + node * 1056 + lane * 33;
    float ok = 0.f, ov = 0.f;
#pragma unroll
    for (int d = 0; d < 32; ++d) {
        const float ak = __shfl_sync(FULL_MASK, xk, d);
        const float av = __shfl_sync(FULL_MASK, xv, d);
        const float w  = wrow[d];
        ok = fmaf(ak, w, ok);
        ov = fmaf(av, w, ov);
    }
    const float bl = pb[node * 32 + lane];
    ok += bl;
    ov += bl;

    const float th = pth[node * 32 + lane];
    const float ta = pta[node * 32 + lane];
    const float vr = pvr[node * 32 + lane];
    const float sk = (xk >= th) ? 1.f : 0.f;
    const float va = xk * (1.f - sk) + vr * sk;
    const float v2 = fmaf(ta, va, xv);
    const float sv = (v2 >= th) ? 1.f : 0.f;

    xk = ok * sk;
    xv = ov * sv;
}

__global__ __launch_bounds__(256) void tree_kernel(
    const float* __restrict__ key_value,
    const float* __restrict__ W,
    const float* __restrict__ bvec,
    const float* __restrict__ thr,
    const float* __restrict__ tau,
    const float* __restrict__ vres)
{
    extern __shared__ float smem[];
    float* Ws  = smem;                 // 15 * 1056 = 15840 floats
    float* pb  = smem + 15 * 1056;     // 480 each
    float* pth = pb  + 480;
    float* pta = pth + 480;
    float* pvr = pta + 480;
    float* ks  = pvr + 480;            // 8*32 merge buffers
    float* vs  = ks  + 256;

    const int tid  = threadIdx.x;
    const int lane = tid & 31;
    const int w    = tid >> 5;         // warp id = node index within level
    const int b    = blockIdx.x >> 3;
    const int h    = blockIdx.x & 7;

    // ---- batched prefetch: all W (3840 float4) + all params ------------------
    const float4* __restrict__ W4 = reinterpret_cast<const float4*>(W);
#pragma unroll
    for (int i = tid; i < 3840; i += 256) {
        const float4 wv = W4[i];
        const int node = i >> 8;        // 256 float4 per node
        const int rem  = i & 255;
        const int o    = rem >> 3;      // 8 float4 per row
        const int d4   = (rem & 7) << 2;
        float* dst = &Ws[node * 1056 + o * 33 + d4];
        dst[0] = wv.x; dst[1] = wv.y; dst[2] = wv.z; dst[3] = wv.w;
    }
#pragma unroll
    for (int i = tid; i < 480; i += 256) {
        pb[i]  = __ldg(&bvec[i]);
        pth[i] = __ldg(&thr[i]);
        pta[i] = __ldg(&tau[i]);
        pvr[i] = __ldg(&vres[i]);
    }

    // leaf w: key_value[b, w, h*32 + lane]  (independent of smem fill)
    float xk = __ldg(&key_value[(b * 16 + w) * 256 + h * 32 + lane]);
    float xv = xk;

    __syncthreads();

    // ---- level 1: 8 nodes (7..14), all warps active --------------------------
    node_step_smem(xk, xv, 7 + w, lane, Ws, pb, pth, pta, pvr);
    ks[w * 32 + lane] = xk; vs[w * 32 + lane] = xv;
    __syncthreads();

    // ---- level 2: 4 nodes (3..6) ---------------------------------------------
    if (w < 4) {
        xk = 0.5f * (ks[(2 * w) * 32 + lane] + ks[(2 * w + 1) * 32 + lane]);
        xv = 0.5f * (vs[(2 * w) * 32 + lane] + vs[(2 * w + 1) * 32 + lane]);
        node_step_smem(xk, xv, 3 + w, lane, Ws, pb, pth, pta, pvr);
    }
    __syncthreads();
    if (w < 4) { ks[w * 32 + lane] = xk; vs[w * 32 + lane] = xv; }
    __syncthreads();

    // ---- level 3: 2 nodes (1..2) ---------------------------------------------
    if (w < 2) {
        xk = 0.5f * (ks[(2 * w) * 32 + lane] + ks[(2 * w + 1) * 32 + lane]);
        xv = 0.5f * (vs[(2 * w) * 32 + lane] + vs[(2 * w + 1) * 32 + lane]);
        node_step_smem(xk, xv, 1 + w, lane, Ws, pb, pth, pta, pvr);
    }
    __syncthreads();
    if (w < 2) { ks[w * 32 + lane] = xk; vs[w * 32 + lane] = xv; }
    __syncthreads();

    // ---- level 4: root node 0 --------------------------------------------------
    if (w == 0) {
        xk = 0.5f * (ks[0 * 32 + lane] + ks[1 * 32 + lane]);
        xv = 0.5f * (vs[0 * 32 + lane] + vs[1 * 32 + lane]);
        node_step_smem(xk, xv, 0, lane, Ws, pb, pth, pta, pvr);
        // softmax over a single tree node == 1.0 -> attn_out = tree_v broadcast
        g_tv[b * 256 + h * 32 + lane] = xv;
    }
}

// ---------------------------------------------------------------------------
// Kernel B: fused residual-add + LayerNorm. One warp per TWO rows (D=256) —
// the empirically best config (regs ~40, occ ~58%, DRAM 73.5%).
// 268 MB mandatory HBM traffic.
// ---------------------------------------------------------------------------
__global__ __launch_bounds__(256) void ln_kernel(
    const float* __restrict__ query,
    const float* __restrict__ gamma,
    const float* __restrict__ beta,
    float* __restrict__ out)
{
    const int  lane = threadIdx.x & 31;
    const long long warp = (long long)blockIdx.x * 8 + (threadIdx.x >> 5);
    const long long r0 = warp * 2;          // rows r0, r0+1 (same batch)
    const int  b = (int)(r0 >> 13);

    const float4* __restrict__ q0r = reinterpret_cast<const float4*>(query) + r0 * 64;
    const float4* __restrict__ q1r = q0r + 64;
    const float4* __restrict__ tvr = reinterpret_cast<const float4*>(g_tv) + b * 64;
    const float4* __restrict__ g4  = reinterpret_cast<const float4*>(gamma);
    const float4* __restrict__ be4 = reinterpret_cast<const float4*>(beta);

    // 4 independent row loads in flight
    const float4 qa0 = __ldg(&q0r[lane]);
    const float4 qa1 = __ldg(&q0r[lane + 32]);
    const float4 qb0 = __ldg(&q1r[lane]);
    const float4 qb1 = __ldg(&q1r[lane + 32]);
    const float4 t0  = tvr[lane];
    const float4 t1  = tvr[lane + 32];

    float4 xa0 = make_float4(qa0.x + t0.x, qa0.y + t0.y, qa0.z + t0.z, qa0.w + t0.w);
    float4 xa1 = make_float4(qa1.x + t1.x, qa1.y + t1.y, qa1.z + t1.z, qa1.w + t1.w);
    float4 xb0 = make_float4(qb0.x + t0.x, qb0.y + t0.y, qb0.z + t0.z, qb0.w + t0.w);
    float4 xb1 = make_float4(qb1.x + t1.x, qb1.y + t1.y, qb1.z + t1.z, qb1.w + t1.w);

    float sa  = xa0.x + xa0.y + xa0.z + xa0.w + xa1.x + xa1.y + xa1.z + xa1.w;
    float ssa = xa0.x*xa0.x + xa0.y*xa0.y + xa0.z*xa0.z + xa0.w*xa0.w
              + xa1.x*xa1.x + xa1.y*xa1.y + xa1.z*xa1.z + xa1.w*xa1.w;
    float sb  = xb0.x + xb0.y + xb0.z + xb0.w + xb1.x + xb1.y + xb1.z + xb1.w;
    float ssb = xb0.x*xb0.x + xb0.y*xb0.y + xb0.z*xb0.z + xb0.w*xb0.w
              + xb1.x*xb1.x + xb1.y*xb1.y + xb1.z*xb1.z + xb1.w*xb1.w;

#pragma unroll
    for (int off = 16; off > 0; off >>= 1) {
        sa  += __shfl_xor_sync(FULL_MASK, sa,  off);
        ssa += __shfl_xor_sync(FULL_MASK, ssa, off);
        sb  += __shfl_xor_sync(FULL_MASK, sb,  off);
        ssb += __shfl_xor_sync(FULL_MASK, ssb, off);
    }

    const float ma   = sa * (1.f / 256.f);
    const float inva = rsqrtf(ssa * (1.f / 256.f) - ma * ma + 1e-5f);
    const float mb   = sb * (1.f / 256.f);
    const float invb = rsqrtf(ssb * (1.f / 256.f) - mb * mb + 1e-5f);

    const float4 g0 = __ldg(&g4[lane]);
    const float4 g1 = __ldg(&g4[lane + 32]);
    const float4 b0 = __ldg(&be4[lane]);
    const float4 b1 = __ldg(&be4[lane + 32]);

    float4 ya0, ya1, yb0, yb1;
    ya0.x = fmaf((xa0.x - ma) * inva, g0.x, b0.x);
    ya0.y = fmaf((xa0.y - ma) * inva, g0.y, b0.y);
    ya0.z = fmaf((xa0.z - ma) * inva, g0.z, b0.z);
    ya0.w = fmaf((xa0.w - ma) * inva, g0.w, b0.w);
    ya1.x = fmaf((xa1.x - ma) * inva, g1.x, b1.x);
    ya1.y = fmaf((xa1.y - ma) * inva, g1.y, b1.y);
    ya1.z = fmaf((xa1.z - ma) * inva, g1.z, b1.z);
    ya1.w = fmaf((xa1.w - ma) * inva, g1.w, b1.w);
    yb0.x = fmaf((xb0.x - mb) * invb, g0.x, b0.x);
    yb0.y = fmaf((xb0.y - mb) * invb, g0.y, b0.y);
    yb0.z = fmaf((xb0.z - mb) * invb, g0.z, b0.z);
    yb0.w = fmaf((xb0.w - mb) * invb, g0.w, b0.w);
    yb1.x = fmaf((xb1.x - mb) * invb, g1.x, b1.x);
    yb1.y = fmaf((xb1.y - mb) * invb, g1.y, b1.y);
    yb1.z = fmaf((xb1.z - mb) * invb, g1.z, b1.z);
    yb1.w = fmaf((xb1.w - mb) * invb, g1.w, b1.w);

    float4* __restrict__ o0 = reinterpret_cast<float4*>(out) + r0 * 64;
    float4* __restrict__ o1 = o0 + 64;
    o0[lane]      = ya0;
    o0[lane + 32] = ya1;
    o1[lane]      = yb0;
    o1[lane + 32] = yb1;
}

// ---------------------------------------------------------------------------
// Inputs (metadata order): query, key_value, W, b, thr, tau, vres, gamma, beta
// Output: float32, 16*8192*256 elements
// ---------------------------------------------------------------------------
extern "C" void kernel_launch(void* const* d_in, const int* in_sizes, int n_in,
                              void* d_out, int out_size)
{
    (void)in_sizes; (void)n_in; (void)out_size;
    const float* query = (const float*)d_in[0];
    const float* kv    = (const float*)d_in[1];
    const float* W     = (const float*)d_in[2];
    const float* bvec  = (const float*)d_in[3];
    const float* thr   = (const float*)d_in[4];
    const float* tau   = (const float*)d_in[5];
    const float* vres  = (const float*)d_in[6];
    const float* gamma = (const float*)d_in[7];
    const float* beta  = (const float*)d_in[8];
    float* out = (float*)d_out;

    // smem: 15*1056 (W) + 4*480 (params) + 2*256 (merge buffers) floats
    const int tree_smem = (15 * 1056 + 4 * 480 + 2 * 256) * (int)sizeof(float);
    static bool attr_set = false;
    if (!attr_set) {
        cudaFuncSetAttribute(tree_kernel,
                             cudaFuncAttributeMaxDynamicSharedMemorySize,
                             tree_smem);
        attr_set = true;
    }

    // Kernel A: one block per (batch, head); warp = node within level
    tree_kernel<<<128, 256, tree_smem>>>(kv, W, bvec, thr, tau, vres);

    // Kernel B: 131072 rows, 2 rows/warp, 8 warps/block -> 8192 blocks
    ln_kernel<<<8192, 256>>>(query, gamma, beta, out);
}